// round 12
// baseline (speedup 1.0000x reference)
#include <cuda_runtime.h>

#define TT 1024
#define EE 256
#define DD 64
#define BB 2
#define JCH 32        // keys per chunk (attn)
#define PROWS 8       // rows per proj block (grid = 256)
#define PCH 32        // e-rows per proj weight chunk
#define NPCH (EE / PCH)

// Scratch (device globals: no allocation allowed in kernel_launch)
__device__ float g_qpb[BB * TT * DD];   // qp + b1, row-major [row][d]
__device__ float g_kpT[BB * DD * TT];   // kp transposed   [b][d][t]
__device__ float g_v  [BB * TT * DD];   // v, row-major    [row][dv]
// split-K partials
__device__ float g_po[2][BB * TT * DD]; // unnormalized o
__device__ float g_pm[2][BB * TT];      // running max
__device__ float g_pl[2][BB * TT];      // denominator

__device__ __forceinline__ void cp16(float* dst, const float* src) {
    unsigned d = (unsigned)__cvta_generic_to_shared(dst);
    asm volatile("cp.async.cg.shared.global [%0], [%1], 16;" :: "r"(d), "l"(src));
}
__device__ __forceinline__ void cp_commit() { asm volatile("cp.async.commit_group;"); }
template <int N>
__device__ __forceinline__ void cp_wait() { asm volatile("cp.async.wait_group %0;" :: "n"(N)); }

// Warp-wide float max via integer redux.sync (f32 redux doesn't exist).
__device__ __forceinline__ float warp_max_f32(float x) {
    unsigned ix = __float_as_uint(x);
    ix = (ix & 0x80000000u) ? ~ix : (ix | 0x80000000u);
    unsigned r = __reduce_max_sync(0xffffffffu, ix);
    r = (r & 0x80000000u) ? (r & 0x7fffffffu) : ~r;
    return __uint_as_float(r);
}

// ---------------------------------------------------------------------------
// Kernel 1 (v4b): projections. 192 thr, 2 rows x 4 cols per thread.
// 3-stage cp.async weight ring -> ONE barrier per chunk. W1 streams into
// free ring buffers during chunks 6/7 compute.
// ---------------------------------------------------------------------------
// dynamic smem (floats):
//   x_sT [EE][PROWS]  = 2048
//   w_s  [3][PCH][192] = 18432   (after loop: w_s+12288 = W1 rows 0..95,
//                                 w_s[0..2047] = W1 rows 96..127)
//   q_sT [DD][PROWS]  = 512
//   k_sT [DD][PROWS]  = 512
#define PXo  0
#define PWo  (PXo + EE * PROWS)
#define PQo  (PWo + 3 * PCH * 192)
#define PKo  (PQo + DD * PROWS)
#define PROJ_SMEM_FLOATS (PKo + DD * PROWS + 4)
#define PROJ_SMEM_BYTES  (PROJ_SMEM_FLOATS * 4)

__global__ __launch_bounds__(192, 2) void proj_kernel(
    const float* __restrict__ x,
    const float* __restrict__ Wq, const float* __restrict__ bq,
    const float* __restrict__ Wk, const float* __restrict__ bk,
    const float* __restrict__ Wv, const float* __restrict__ bv,
    const float* __restrict__ W1, const float* __restrict__ b1)
{
    extern __shared__ __align__(16) float sm[];
    float* x_sT = sm + PXo;       // [e][row]
    float* w_s  = sm + PWo;       // [3][e][col(192)]
    float* q_sT = sm + PQo;       // [dd][row]
    float* k_sT = sm + PKo;       // [dd][row]

    const int r0 = blockIdx.x * PROWS;
    const int t  = threadIdx.x;

    const float* Wmat[3] = { Wq, Wk, Wv };

    // helper pattern: stage weight chunk e0 into buffer `buf`
    // (1536 float4s over 192 threads = 8 per thread)
#define STAGE_W(e0, buf) do {                                            \
        float* _db = w_s + (buf) * PCH * 192;                            \
        _Pragma("unroll")                                                \
        for (int u = 0; u < 8; u++) {                                    \
            int idx = t + u * 192;                                       \
            int rw = idx / 48, col4 = idx % 48;                          \
            int wch = col4 >> 4, c4 = col4 & 15;                         \
            cp16(&_db[rw * 192 + col4 * 4],                              \
                 Wmat[wch] + (((e0) + rw) * 16 + c4) * 4);               \
        }                                                                \
        cp_commit();                                                     \
    } while (0)

    STAGE_W(0, 0);

    // stage x transposed: x_sT[e][row]
    {
        const float4* x4 = (const float4*)(x + r0 * EE);
        for (int idx = t; idx < PROWS * EE / 4; idx += 192) {
            int row = idx >> 6, e4 = idx & 63;
            float4 v = x4[row * 64 + e4];
            x_sT[(e4 * 4 + 0) * PROWS + row] = v.x;
            x_sT[(e4 * 4 + 1) * PROWS + row] = v.y;
            x_sT[(e4 * 4 + 2) * PROWS + row] = v.z;
            x_sT[(e4 * 4 + 3) * PROWS + row] = v.w;
        }
    }
    STAGE_W(PCH, 1);

    const int which = t >> 6;          // 0..2
    const int d4    = (t >> 2) & 15;   // 0..15
    const int ra    = (t & 3) * 2;     // rows ra, ra+1

    float4 acc0 = make_float4(0.f, 0.f, 0.f, 0.f);
    float4 acc1 = make_float4(0.f, 0.f, 0.f, 0.f);

    for (int c = 0; c < NPCH; c++) {
        cp_wait<1>();                 // chunk c complete (newest may fly)
        __syncthreads();              // single barrier per chunk (3-stage ring)

        if (c + 2 < NPCH) {
            STAGE_W((c + 2) * PCH, (c + 2) % 3);
        } else if (c == NPCH - 2) {
            // W1 rows 0..95 (1536 float4s) into free buf (c+2)%3
            float* dst = w_s + ((c + 2) % 3) * PCH * 192;
            #pragma unroll
            for (int u = 0; u < 8; u++) {
                int idx = t + u * 192;
                cp16(&dst[idx * 4], W1 + idx * 4);
            }
            cp_commit();
        } else {
            // c == NPCH-1: W1 rows 96..127 (512 float4s) into free buf (c+2)%3
            float* dst = w_s + ((c + 2) % 3) * PCH * 192;
            for (int idx = t; idx < 512; idx += 192)
                cp16(&dst[idx * 4], W1 + 6144 + idx * 4);
            cp_commit();
        }

        const float* wb = w_s + (c % 3) * PCH * 192 + which * 64 + d4 * 4;
        const float* xb = x_sT + c * PCH * PROWS + ra;
        #pragma unroll
        for (int e = 0; e < PCH; e++) {
            float4 w4 = *(const float4*)(wb + e * 192);
            float2 x2 = *(const float2*)(xb + e * PROWS);
            acc0.x = fmaf(x2.x, w4.x, acc0.x);
            acc0.y = fmaf(x2.x, w4.y, acc0.y);
            acc0.z = fmaf(x2.x, w4.z, acc0.z);
            acc0.w = fmaf(x2.x, w4.w, acc0.w);
            acc1.x = fmaf(x2.y, w4.x, acc1.x);
            acc1.y = fmaf(x2.y, w4.y, acc1.y);
            acc1.z = fmaf(x2.y, w4.z, acc1.z);
            acc1.w = fmaf(x2.y, w4.w, acc1.w);
        }
    }
#undef STAGE_W

    // W1 buffer locations after the loop:
    //   rows 0..95  at buf (NPCH)%3   = 8%3 = 2  -> w_s + 2*6144
    //   rows 96..127 at buf (NPCH+1)%3 = 0       -> w_s + 0
    const float* w1a = w_s + 2 * PCH * 192;   // rows 0..95
    const float* w1b = w_s;                   // rows 96..127

    // Phase A epilogue
    {
        const float* bias3 = (which == 0) ? bq : (which == 1 ? bk : bv);
        float4 bias = ((const float4*)bias3)[d4];
        float4 o0, o1;
        o0.x = acc0.x + bias.x; o0.y = acc0.y + bias.y;
        o0.z = acc0.z + bias.z; o0.w = acc0.w + bias.w;
        o1.x = acc1.x + bias.x; o1.y = acc1.y + bias.y;
        o1.z = acc1.z + bias.z; o1.w = acc1.w + bias.w;
        if (which == 2) {
            *(float4*)&g_v[(r0 + ra    ) * DD + d4 * 4] = o0;
            *(float4*)&g_v[(r0 + ra + 1) * DD + d4 * 4] = o1;
        } else {
            float* dst = (which == 0) ? q_sT : k_sT;
            dst[(d4 * 4 + 0) * PROWS + ra]     = fmaxf(o0.x, 0.f);
            dst[(d4 * 4 + 1) * PROWS + ra]     = fmaxf(o0.y, 0.f);
            dst[(d4 * 4 + 2) * PROWS + ra]     = fmaxf(o0.z, 0.f);
            dst[(d4 * 4 + 3) * PROWS + ra]     = fmaxf(o0.w, 0.f);
            dst[(d4 * 4 + 0) * PROWS + ra + 1] = fmaxf(o1.x, 0.f);
            dst[(d4 * 4 + 1) * PROWS + ra + 1] = fmaxf(o1.y, 0.f);
            dst[(d4 * 4 + 2) * PROWS + ra + 1] = fmaxf(o1.z, 0.f);
            dst[(d4 * 4 + 3) * PROWS + ra + 1] = fmaxf(o1.w, 0.f);
        }
    }
    cp_wait<0>();
    __syncthreads();

    // Phase B: qp (with b1) and kp; threads 0..127, 2 rows x 4 cols
    if (t < 128) {
        const int sel = t >> 6;            // 0 = qp, 1 = kp
        const int d4b = (t >> 2) & 15;
        const int rb  = (t & 3) * 2;

        float4 a0 = make_float4(0.f, 0.f, 0.f, 0.f);
        float4 a1 = make_float4(0.f, 0.f, 0.f, 0.f);

        if (sel == 0) {
            #pragma unroll 16
            for (int e = 0; e < DD; e++) {
                float4 w4 = *(const float4*)(w1a + e * 64 + d4b * 4);
                float2 x2 = *(const float2*)(q_sT + e * PROWS + rb);
                a0.x = fmaf(x2.x, w4.x, a0.x); a0.y = fmaf(x2.x, w4.y, a0.y);
                a0.z = fmaf(x2.x, w4.z, a0.z); a0.w = fmaf(x2.x, w4.w, a0.w);
                a1.x = fmaf(x2.y, w4.x, a1.x); a1.y = fmaf(x2.y, w4.y, a1.y);
                a1.z = fmaf(x2.y, w4.z, a1.z); a1.w = fmaf(x2.y, w4.w, a1.w);
            }
            float4 bias = ((const float4*)b1)[d4b];
            float4 o0, o1;
            o0.x = a0.x + bias.x; o0.y = a0.y + bias.y;
            o0.z = a0.z + bias.z; o0.w = a0.w + bias.w;
            o1.x = a1.x + bias.x; o1.y = a1.y + bias.y;
            o1.z = a1.z + bias.z; o1.w = a1.w + bias.w;
            *(float4*)&g_qpb[(r0 + rb    ) * DD + d4b * 4] = o0;
            *(float4*)&g_qpb[(r0 + rb + 1) * DD + d4b * 4] = o1;
        } else {
            #pragma unroll 16
            for (int e = 0; e < 32; e++) {
                float4 w4 = *(const float4*)(w1a + (64 + e) * 64 + d4b * 4);
                float2 x2 = *(const float2*)(k_sT + e * PROWS + rb);
                a0.x = fmaf(x2.x, w4.x, a0.x); a0.y = fmaf(x2.x, w4.y, a0.y);
                a0.z = fmaf(x2.x, w4.z, a0.z); a0.w = fmaf(x2.x, w4.w, a0.w);
                a1.x = fmaf(x2.y, w4.x, a1.x); a1.y = fmaf(x2.y, w4.y, a1.y);
                a1.z = fmaf(x2.y, w4.z, a1.z); a1.w = fmaf(x2.y, w4.w, a1.w);
            }
            #pragma unroll 16
            for (int e = 32; e < DD; e++) {
                float4 w4 = *(const float4*)(w1b + (e - 32) * 64 + d4b * 4);
                float2 x2 = *(const float2*)(k_sT + e * PROWS + rb);
                a0.x = fmaf(x2.x, w4.x, a0.x); a0.y = fmaf(x2.x, w4.y, a0.y);
                a0.z = fmaf(x2.x, w4.z, a0.z); a0.w = fmaf(x2.x, w4.w, a0.w);
                a1.x = fmaf(x2.y, w4.x, a1.x); a1.y = fmaf(x2.y, w4.y, a1.y);
                a1.z = fmaf(x2.y, w4.z, a1.z); a1.w = fmaf(x2.y, w4.w, a1.w);
            }
            const int b  = r0 >> 10;
            const int tb = (r0 & 1023) + rb;
            *(float2*)&g_kpT[(b * DD + d4b * 4 + 0) * TT + tb] = make_float2(a0.x, a1.x);
            *(float2*)&g_kpT[(b * DD + d4b * 4 + 1) * TT + tb] = make_float2(a0.y, a1.y);
            *(float2*)&g_kpT[(b * DD + d4b * 4 + 2) * TT + tb] = make_float2(a0.z, a1.z);
            *(float2*)&g_kpT[(b * DD + d4b * 4 + 3) * TT + tb] = make_float2(a0.w, a1.w);
        }
    }
}

// ---------------------------------------------------------------------------
// Kernel 2 (v3): split-K attention. 4 queries/warp, JCH=32, 1 key/lane,
// 8 queries/block (64 thr), grid 512 — ~36KB smem -> 5+ blocks/SM, one wave.
// ---------------------------------------------------------------------------
#define SMEM_FLOATS (2 * DD * JCH + 2 * JCH * DD + 2 * JCH * 4 + 8 * DD + DD + 4)
#define SMEM_BYTES  (SMEM_FLOATS * 4)

__global__ __launch_bounds__(64, 5) void attn_kernel(
    const float* __restrict__ W2)
{
    extern __shared__ __align__(16) float smem[];
    float (*kp_s)[DD][JCH]   = (float (*)[DD][JCH])smem;                     // [2][d][j]
    float (*v_s)[JCH][DD]    = (float (*)[JCH][DD])(smem + 2 * DD * JCH);    // [2][j][dv]
    float (*p_s)[JCH][4]     = (float (*)[JCH][4])(smem + 4 * DD * JCH);     // [2 warps][j][q]
    float (*q_s)[DD]         = (float (*)[DD])(smem + 4 * DD * JCH + 2 * JCH * 4); // [8][d]
    float *w2_s              = smem + 4 * DD * JCH + 2 * JCH * 4 + 8 * DD;

    const int bid  = (int)blockIdx.x;
    const int oct  = ((int)gridDim.x / 2 - 1) - (bid >> 1);   // heavy-first
    const int s    = bid & 1;                                  // split id
    const int b    = oct >> 7;                                 // 128 octs/batch
    const int i0   = (oct & 127) * 8;
    const int t    = threadIdx.x;
    const int wid  = t >> 5;
    const int lane = t & 31;
    const int iq0  = i0 + wid * 4;      // this warp's 4 query rows

    if (t < DD) w2_s[t] = W2[t];
    // stage 8 query rows (128 float4s over 64 threads)
    ((float4*)q_s)[t]      = ((const float4*)(g_qpb + (b * TT + i0) * DD))[t];
    ((float4*)q_s)[t + 64] = ((const float4*)(g_qpb + (b * TT + i0) * DD))[t + 64];

    const float* kpT_b = g_kpT + b * DD * TT;
    const float* v_b   = g_v   + b * TT * DD;

    const int nch = i0 / JCH + 1;        // covers keys <= i0+7

    // stage chunk: kp 512 f4 + v 512 f4 over 64 threads
#define STAGE_CHUNK(j0, buf) do {                                        \
        _Pragma("unroll")                                                \
        for (int u = 0; u < 8; u++) {                                    \
            int idx = t + u * 64;                                        \
            int d = idx >> 3, cc = idx & 7;                              \
            cp16(&kp_s[buf][d][cc * 4], kpT_b + d * TT + (j0) + cc * 4); \
        }                                                                \
        _Pragma("unroll")                                                \
        for (int u = 0; u < 8; u++) {                                    \
            int idx = t + u * 64;                                        \
            cp16(&v_s[buf][0][0] + idx * 4, v_b + (j0) * DD + idx * 4);  \
        }                                                                \
        cp_commit();                                                     \
    } while (0)

    if (s < nch) STAGE_CHUNK(s * JCH, 0);
    else cp_commit();

    const float NEG_INF = __int_as_float(0xff800000);
    float m[4], l[4], ox[4], oy[4];
    #pragma unroll
    for (int qq = 0; qq < 4; qq++) { m[qq] = NEG_INF; l[qq] = 0.f; ox[qq] = 0.f; oy[qq] = 0.f; }

    const float4* w24 = (const float4*)w2_s;
    const float4* q4[4];
    #pragma unroll
    for (int qq = 0; qq < 4; qq++) q4[qq] = (const float4*)q_s[wid * 4 + qq];

    for (int c = s; c < nch; c += 2) {
        cp_wait<0>();
        __syncthreads();                 // chunk c staged & visible

        if (c + 2 < nch)
            STAGE_CHUNK((c + 2) * JCH, ((c >> 1) + 1) & 1);

        const int j0 = c * JCH;
        const int cb = (c >> 1) & 1;
        const float (*kp)[JCH] = kp_s[cb];
        const float (*vv)[DD]  = v_s[cb];

        // ---- scores: key j0+lane, 4 queries ----
        float ae[4] = {0.f, 0.f, 0.f, 0.f};
        float ao[4] = {0.f, 0.f, 0.f, 0.f};
        #pragma unroll
        for (int d4 = 0; d4 < 16; d4++) {
            float4 w4 = w24[d4];
            float k0 = kp[4 * d4 + 0][lane];
            float k1 = kp[4 * d4 + 1][lane];
            float k2 = kp[4 * d4 + 2][lane];
            float k3 = kp[4 * d4 + 3][lane];
            #pragma unroll
            for (int qq = 0; qq < 4; qq++) {
                float4 q = q4[qq][d4];
                ae[qq] = fmaf(fmaxf(q.x + k0, 0.f), w4.x, ae[qq]);
                ao[qq] = fmaf(fmaxf(q.y + k1, 0.f), w4.y, ao[qq]);
                ae[qq] = fmaf(fmaxf(q.z + k2, 0.f), w4.z, ae[qq]);
                ao[qq] = fmaf(fmaxf(q.w + k3, 0.f), w4.w, ao[qq]);
            }
        }

        // ---- online softmax, lane-local denominators ----
        const int j = j0 + lane;
        float pv[4];
        #pragma unroll
        for (int qq = 0; qq < 4; qq++) {
            float sq   = (j <= iq0 + qq) ? (ae[qq] + ao[qq]) : NEG_INF;
            float nm   = fmaxf(m[qq], warp_max_f32(sq));
            float corr = __expf(m[qq] - nm);
            float p    = __expf(sq - nm);
            l[qq]  = fmaf(l[qq], corr, p);
            ox[qq] *= corr; oy[qq] *= corr;
            m[qq]  = nm;
            pv[qq] = p;
        }
        *(float4*)&p_s[wid][lane][0] = make_float4(pv[0], pv[1], pv[2], pv[3]);
        __syncwarp();

        // ---- PV: per key, one LDS.128 p-broadcast + one LDS.64 v, 8 FMA ----
        #pragma unroll
        for (int jj = 0; jj < JCH; jj++) {
            float4 p4 = *(const float4*)&p_s[wid][jj][0];
            float2 v2 = *(const float2*)&vv[jj][2 * lane];
            ox[0] = fmaf(p4.x, v2.x, ox[0]); oy[0] = fmaf(p4.x, v2.y, oy[0]);
            ox[1] = fmaf(p4.y, v2.x, ox[1]); oy[1] = fmaf(p4.y, v2.y, oy[1]);
            ox[2] = fmaf(p4.z, v2.x, ox[2]); oy[2] = fmaf(p4.z, v2.y, oy[2]);
            ox[3] = fmaf(p4.w, v2.x, ox[3]); oy[3] = fmaf(p4.w, v2.y, oy[3]);
        }
    }
#undef STAGE_CHUNK

    // final cross-lane denominator sums + partial writes
    #pragma unroll
    for (int qq = 0; qq < 4; qq++) {
        float lt = l[qq];
        #pragma unroll
        for (int off = 16; off; off >>= 1)
            lt += __shfl_xor_sync(0xffffffffu, lt, off);
        const int iq = iq0 + qq;
        *(float2*)&g_po[s][(b * TT + iq) * DD + 2 * lane] = make_float2(ox[qq], oy[qq]);
        if (lane == 0) {
            g_pm[s][b * TT + iq] = m[qq];
            g_pl[s][b * TT + iq] = lt;
        }
    }
}

// ---------------------------------------------------------------------------
// Kernel 3: combine the two split-K partials. 4 rows/block x 512 blocks.
// ---------------------------------------------------------------------------
__global__ __launch_bounds__(128) void combine_kernel(float* __restrict__ out)
{
    const int row  = blockIdx.x * 4 + (threadIdx.x >> 5);
    const int lane = threadIdx.x & 31;

    float m0 = g_pm[0][row], l0 = g_pl[0][row];
    float m1 = g_pm[1][row], l1 = g_pl[1][row];
    float M  = fmaxf(m0, m1);
    float c0 = __expf(m0 - M);
    float c1 = __expf(m1 - M);          // empty split: m1=-inf -> c1=0
    float inv = 1.0f / fmaf(l0, c0, l1 * c1);

    float2 o0 = *(const float2*)&g_po[0][row * DD + 2 * lane];
    float2 o1 = *(const float2*)&g_po[1][row * DD + 2 * lane];
    *(float2*)&out[row * DD + 2 * lane] =
        make_float2(fmaf(o0.x, c0, o1.x * c1) * inv,
                    fmaf(o0.y, c0, o1.y * c1) * inv);
}

// ---------------------------------------------------------------------------
extern "C" void kernel_launch(void* const* d_in, const int* in_sizes, int n_in,
                              void* d_out, int out_size)
{
    const float* x  = (const float*)d_in[0];
    const float* Wq = (const float*)d_in[1];
    const float* bq = (const float*)d_in[2];
    const float* Wk = (const float*)d_in[3];
    const float* bk = (const float*)d_in[4];
    const float* Wv = (const float*)d_in[5];
    const float* bv = (const float*)d_in[6];
    const float* W1 = (const float*)d_in[7];
    const float* b1 = (const float*)d_in[8];
    const float* W2 = (const float*)d_in[9];
    // b2 (d_in[10]) is a constant shift on scores: cancels in softmax.

    (void)cudaFuncSetAttribute(proj_kernel,
                               cudaFuncAttributeMaxDynamicSharedMemorySize,
                               PROJ_SMEM_BYTES);
    (void)cudaFuncSetAttribute(attn_kernel,
                               cudaFuncAttributeMaxDynamicSharedMemorySize,
                               SMEM_BYTES);

    proj_kernel<<<BB * TT / PROWS, 192, PROJ_SMEM_BYTES>>>(
        x, Wq, bq, Wk, bk, Wv, bv, W1, b1);
    attn_kernel<<<BB * TT / 8 * 2, 64, SMEM_BYTES>>>(W2);
    combine_kernel<<<BB * TT / 4, 128>>>((float*)d_out);
}

// round 13
// speedup vs baseline: 1.1446x; 1.1446x over previous
#include <cuda_runtime.h>

#define TT 1024
#define EE 256
#define DD 64
#define BB 2
#define JCH 64        // keys per chunk (attn)
#define PROWS 8       // rows per proj block (grid = 256)
#define PCH 32        // e-rows per proj weight chunk
#define NPCH (EE / PCH)

// Scratch (device globals: no allocation allowed in kernel_launch)
__device__ float g_qpb[BB * TT * DD];   // qp + b1, row-major [row][d]
__device__ float g_kpT[BB * DD * TT];   // kp transposed   [b][d][t]
__device__ float g_v  [BB * TT * DD];   // v, row-major    [row][dv]
// split-K partials
__device__ float g_po[2][BB * TT * DD]; // unnormalized o
__device__ float g_pm[2][BB * TT];      // running max
__device__ float g_pl[2][BB * TT];      // denominator

__device__ __forceinline__ void cp16(float* dst, const float* src) {
    unsigned d = (unsigned)__cvta_generic_to_shared(dst);
    asm volatile("cp.async.cg.shared.global [%0], [%1], 16;" :: "r"(d), "l"(src));
}
__device__ __forceinline__ void cp_commit() { asm volatile("cp.async.commit_group;"); }
template <int N>
__device__ __forceinline__ void cp_wait() { asm volatile("cp.async.wait_group %0;" :: "n"(N)); }

// Warp-wide float max via integer redux.sync (f32 redux doesn't exist).
__device__ __forceinline__ float warp_max_f32(float x) {
    unsigned ix = __float_as_uint(x);
    ix = (ix & 0x80000000u) ? ~ix : (ix | 0x80000000u);
    unsigned r = __reduce_max_sync(0xffffffffu, ix);
    r = (r & 0x80000000u) ? (r & 0x7fffffffu) : ~r;
    return __uint_as_float(r);
}

// ---------------------------------------------------------------------------
// Kernel 1 (v4c): projections. 192 thr; Phase A thread = 4 rows x 2 cols so
// the weight read is LDS.64 (1-2 shared wavefronts) and x is one broadcast
// LDS.128 — cuts shared wavefronts per 8 FMAs from ~5 to ~2-3.
// 3-stage cp.async ring; W1 streams into free ring buffers (chunks 6/7).
// ---------------------------------------------------------------------------
#define PXo  0
#define PWo  (PXo + EE * PROWS)
#define PQo  (PWo + 3 * PCH * 192)
#define PKo  (PQo + DD * PROWS)
#define PROJ_SMEM_FLOATS (PKo + DD * PROWS + 4)
#define PROJ_SMEM_BYTES  (PROJ_SMEM_FLOATS * 4)

__global__ __launch_bounds__(192, 2) void proj_kernel(
    const float* __restrict__ x,
    const float* __restrict__ Wq, const float* __restrict__ bq,
    const float* __restrict__ Wk, const float* __restrict__ bk,
    const float* __restrict__ Wv, const float* __restrict__ bv,
    const float* __restrict__ W1, const float* __restrict__ b1)
{
    extern __shared__ __align__(16) float sm[];
    float* x_sT = sm + PXo;       // [e][row]
    float* w_s  = sm + PWo;       // [3][e][col(192)]
    float* q_sT = sm + PQo;       // [dd][row]
    float* k_sT = sm + PKo;       // [dd][row]

    const int r0 = blockIdx.x * PROWS;
    const int t  = threadIdx.x;

    const float* Wmat[3] = { Wq, Wk, Wv };

#define STAGE_W(e0, buf) do {                                            \
        float* _db = w_s + (buf) * PCH * 192;                            \
        _Pragma("unroll")                                                \
        for (int u = 0; u < 8; u++) {                                    \
            int idx = t + u * 192;                                       \
            int rw = idx / 48, col4 = idx % 48;                          \
            int wch = col4 >> 4, c4 = col4 & 15;                         \
            cp16(&_db[rw * 192 + col4 * 4],                              \
                 Wmat[wch] + (((e0) + rw) * 16 + c4) * 4);               \
        }                                                                \
        cp_commit();                                                     \
    } while (0)

    STAGE_W(0, 0);

    // stage x transposed: x_sT[e][row]
    {
        const float4* x4 = (const float4*)(x + r0 * EE);
        for (int idx = t; idx < PROWS * EE / 4; idx += 192) {
            int row = idx >> 6, e4 = idx & 63;
            float4 v = x4[row * 64 + e4];
            x_sT[(e4 * 4 + 0) * PROWS + row] = v.x;
            x_sT[(e4 * 4 + 1) * PROWS + row] = v.y;
            x_sT[(e4 * 4 + 2) * PROWS + row] = v.z;
            x_sT[(e4 * 4 + 3) * PROWS + row] = v.w;
        }
    }
    STAGE_W(PCH, 1);

    // Phase A map: which[3] x colpair[32] x rowgroup[2] -> 4 rows x 2 cols
    const int which = t >> 6;            // 0..2
    const int cp    = (t >> 1) & 31;     // 0..31 (cols cp*2, cp*2+1)
    const int rg    = (t & 1) * 4;       // rows rg..rg+3

    float2 a[4];
    #pragma unroll
    for (int r = 0; r < 4; r++) a[r] = make_float2(0.f, 0.f);

    for (int c = 0; c < NPCH; c++) {
        cp_wait<1>();
        __syncthreads();

        if (c + 2 < NPCH) {
            STAGE_W((c + 2) * PCH, (c + 2) % 3);
        } else if (c == NPCH - 2) {
            float* dst = w_s + ((c + 2) % 3) * PCH * 192;   // W1 rows 0..95
            #pragma unroll
            for (int u = 0; u < 8; u++) {
                int idx = t + u * 192;
                cp16(&dst[idx * 4], W1 + idx * 4);
            }
            cp_commit();
        } else {
            float* dst = w_s + ((c + 2) % 3) * PCH * 192;   // W1 rows 96..127
            for (int idx = t; idx < 512; idx += 192)
                cp16(&dst[idx * 4], W1 + 6144 + idx * 4);
            cp_commit();
        }

        const float* wb = w_s + (c % 3) * PCH * 192 + which * 64 + cp * 2;
        const float* xb = x_sT + c * PCH * PROWS + rg;
        #pragma unroll
        for (int e = 0; e < PCH; e++) {
            float2 w2v = *(const float2*)(wb + e * 192);
            float4 xv  = *(const float4*)(xb + e * PROWS);
            a[0].x = fmaf(xv.x, w2v.x, a[0].x); a[0].y = fmaf(xv.x, w2v.y, a[0].y);
            a[1].x = fmaf(xv.y, w2v.x, a[1].x); a[1].y = fmaf(xv.y, w2v.y, a[1].y);
            a[2].x = fmaf(xv.z, w2v.x, a[2].x); a[2].y = fmaf(xv.z, w2v.y, a[2].y);
            a[3].x = fmaf(xv.w, w2v.x, a[3].x); a[3].y = fmaf(xv.w, w2v.y, a[3].y);
        }
    }
#undef STAGE_W

    // W1 after loop: rows 0..95 in buf2, rows 96..127 in buf0
    const float* w1a = w_s + 2 * PCH * 192;
    const float* w1b = w_s;

    // Phase A epilogue: bias (+relu), write v / q_sT / k_sT
    {
        const float* bias3 = (which == 0) ? bq : (which == 1 ? bk : bv);
        float2 bias2 = *(const float2*)(bias3 + cp * 2);
        #pragma unroll
        for (int r = 0; r < 4; r++) {
            float2 o;
            o.x = a[r].x + bias2.x;
            o.y = a[r].y + bias2.y;
            if (which == 2) {
                *(float2*)&g_v[(r0 + rg + r) * DD + cp * 2] = o;
            } else {
                float* dst = (which == 0) ? q_sT : k_sT;
                dst[(cp * 2 + 0) * PROWS + rg + r] = fmaxf(o.x, 0.f);
                dst[(cp * 2 + 1) * PROWS + rg + r] = fmaxf(o.y, 0.f);
            }
        }
    }
    cp_wait<0>();
    __syncthreads();

    // Phase B: qp (with b1) and kp; threads 0..127, 4 rows x 2 cols
    if (t < 128) {
        const int sel = t >> 6;            // 0 = qp, 1 = kp
        const int cpb = (t >> 1) & 31;
        const int rb  = (t & 1) * 4;

        float2 b2[4];
        #pragma unroll
        for (int r = 0; r < 4; r++) b2[r] = make_float2(0.f, 0.f);

        if (sel == 0) {
            #pragma unroll 16
            for (int e = 0; e < DD; e++) {
                float2 w2v = *(const float2*)(w1a + e * 64 + cpb * 2);
                float4 xv  = *(const float4*)(q_sT + e * PROWS + rb);
                b2[0].x = fmaf(xv.x, w2v.x, b2[0].x); b2[0].y = fmaf(xv.x, w2v.y, b2[0].y);
                b2[1].x = fmaf(xv.y, w2v.x, b2[1].x); b2[1].y = fmaf(xv.y, w2v.y, b2[1].y);
                b2[2].x = fmaf(xv.z, w2v.x, b2[2].x); b2[2].y = fmaf(xv.z, w2v.y, b2[2].y);
                b2[3].x = fmaf(xv.w, w2v.x, b2[3].x); b2[3].y = fmaf(xv.w, w2v.y, b2[3].y);
            }
            float2 bias2 = *(const float2*)((const float*)b1 + cpb * 2);
            #pragma unroll
            for (int r = 0; r < 4; r++) {
                float2 o;
                o.x = b2[r].x + bias2.x;
                o.y = b2[r].y + bias2.y;
                *(float2*)&g_qpb[(r0 + rb + r) * DD + cpb * 2] = o;
            }
        } else {
            #pragma unroll 16
            for (int e = 0; e < 32; e++) {
                float2 w2v = *(const float2*)(w1a + (64 + e) * 64 + cpb * 2);
                float4 xv  = *(const float4*)(k_sT + e * PROWS + rb);
                b2[0].x = fmaf(xv.x, w2v.x, b2[0].x); b2[0].y = fmaf(xv.x, w2v.y, b2[0].y);
                b2[1].x = fmaf(xv.y, w2v.x, b2[1].x); b2[1].y = fmaf(xv.y, w2v.y, b2[1].y);
                b2[2].x = fmaf(xv.z, w2v.x, b2[2].x); b2[2].y = fmaf(xv.z, w2v.y, b2[2].y);
                b2[3].x = fmaf(xv.w, w2v.x, b2[3].x); b2[3].y = fmaf(xv.w, w2v.y, b2[3].y);
            }
            #pragma unroll 16
            for (int e = 32; e < DD; e++) {
                float2 w2v = *(const float2*)(w1b + (e - 32) * 64 + cpb * 2);
                float4 xv  = *(const float4*)(k_sT + e * PROWS + rb);
                b2[0].x = fmaf(xv.x, w2v.x, b2[0].x); b2[0].y = fmaf(xv.x, w2v.y, b2[0].y);
                b2[1].x = fmaf(xv.y, w2v.x, b2[1].x); b2[1].y = fmaf(xv.y, w2v.y, b2[1].y);
                b2[2].x = fmaf(xv.z, w2v.x, b2[2].x); b2[2].y = fmaf(xv.z, w2v.y, b2[2].y);
                b2[3].x = fmaf(xv.w, w2v.x, b2[3].x); b2[3].y = fmaf(xv.w, w2v.y, b2[3].y);
            }
            const int b  = r0 >> 10;
            const int tb = (r0 & 1023) + rb;
            *(float4*)&g_kpT[(b * DD + cpb * 2 + 0) * TT + tb] =
                make_float4(b2[0].x, b2[1].x, b2[2].x, b2[3].x);
            *(float4*)&g_kpT[(b * DD + cpb * 2 + 1) * TT + tb] =
                make_float4(b2[0].y, b2[1].y, b2[2].y, b2[3].y);
        }
    }
}

// ---------------------------------------------------------------------------
// Kernel 2: split-K attention partials — EXACT R9 version (best known).
// ---------------------------------------------------------------------------
#define SMEM_FLOATS (2 * DD * JCH + 2 * JCH * DD + 4 * JCH + 4 * DD + DD + 4)
#define SMEM_BYTES  (SMEM_FLOATS * 4)

__global__ __launch_bounds__(64, 3) void attn_kernel(
    const float* __restrict__ W2)
{
    extern __shared__ __align__(16) float smem[];
    float (*kp_s)[DD][JCH] = (float (*)[DD][JCH])smem;
    float (*v_s)[JCH][DD]  = (float (*)[JCH][DD])(smem + 2 * DD * JCH);
    float (*p_s)[JCH]      = (float (*)[JCH])(smem + 4 * DD * JCH);
    float (*q_s)[DD]       = (float (*)[DD])(smem + 4 * DD * JCH + 4 * JCH);
    float *w2_s            = smem + 4 * DD * JCH + 4 * JCH + 4 * DD;

    const int bid  = (int)blockIdx.x;
    const int quad = ((int)gridDim.x / 2 - 1) - (bid >> 1);
    const int s    = bid & 1;
    const int b    = quad >> 8;
    const int i0   = (quad & 255) * 4;
    const int t    = threadIdx.x;
    const int wid  = t >> 5;
    const int lane = t & 31;
    const int ia   = i0 + wid * 2;
    const int ib   = ia + 1;

    if (t < DD) w2_s[t] = W2[t];
    ((float4*)q_s)[t] = ((const float4*)(g_qpb + (b * TT + i0) * DD))[t];

    const float* kpT_b = g_kpT + b * DD * TT;
    const float* v_b   = g_v   + b * TT * DD;

    const int nch = i0 / JCH + 1;

    if (s < nch) {
        const int j0 = s * JCH;
        #pragma unroll
        for (int u = 0; u < 16; u++) {
            int idx = t + u * 64;
            int d = idx >> 4, cc = idx & 15;
            cp16(&kp_s[0][d][cc * 4], kpT_b + d * TT + j0 + cc * 4);
            cp16(&v_s[0][0][0] + idx * 4, v_b + j0 * DD + idx * 4);
        }
    }
    cp_commit();

    const float NEG_INF = __int_as_float(0xff800000);
    float ma = NEG_INF, la = 0.f, mb = NEG_INF, lb = 0.f;
    float axe = 0.f, aye = 0.f, axo = 0.f, ayo = 0.f;
    float bxe = 0.f, bye = 0.f, bxo = 0.f, byo = 0.f;

    const float4* qa4 = (const float4*)q_s[wid * 2];
    const float4* qb4 = (const float4*)q_s[wid * 2 + 1];
    const float4* w24 = (const float4*)w2_s;

    for (int c = s; c < nch; c += 2) {
        cp_wait<0>();
        __syncthreads();

        if (c + 2 < nch) {
            const int j0n = (c + 2) * JCH;
            const int buf = ((c >> 1) + 1) & 1;
            #pragma unroll
            for (int u = 0; u < 16; u++) {
                int idx = t + u * 64;
                int d = idx >> 4, cc = idx & 15;
                cp16(&kp_s[buf][d][cc * 4], kpT_b + d * TT + j0n + cc * 4);
                cp16(&v_s[buf][0][0] + idx * 4, v_b + j0n * DD + idx * 4);
            }
            cp_commit();
        }

        const int j0 = c * JCH;
        const int cb2 = (c >> 1) & 1;
        const float (*kp)[JCH] = kp_s[cb2];
        const float (*vv_s)[DD] = v_s[cb2];

        float a0 = 0.f, a1 = 0.f, a2 = 0.f, a3 = 0.f;
        float b0 = 0.f, b1 = 0.f, b2 = 0.f, b3 = 0.f;
        #pragma unroll
        for (int d4 = 0; d4 < 16; d4++) {
            float4 w4 = w24[d4];
            float4 qa = qa4[d4];
            float4 qb = qb4[d4];
            float2 k0 = *(const float2*)&kp[4 * d4 + 0][2 * lane];
            float2 k1 = *(const float2*)&kp[4 * d4 + 1][2 * lane];
            float2 k2 = *(const float2*)&kp[4 * d4 + 2][2 * lane];
            float2 k3 = *(const float2*)&kp[4 * d4 + 3][2 * lane];
            a0 = fmaf(fmaxf(qa.x + k0.x, 0.f), w4.x, a0);
            a1 = fmaf(fmaxf(qa.x + k0.y, 0.f), w4.x, a1);
            a2 = fmaf(fmaxf(qa.y + k1.x, 0.f), w4.y, a2);
            a3 = fmaf(fmaxf(qa.y + k1.y, 0.f), w4.y, a3);
            a0 = fmaf(fmaxf(qa.z + k2.x, 0.f), w4.z, a0);
            a1 = fmaf(fmaxf(qa.z + k2.y, 0.f), w4.z, a1);
            a2 = fmaf(fmaxf(qa.w + k3.x, 0.f), w4.w, a2);
            a3 = fmaf(fmaxf(qa.w + k3.y, 0.f), w4.w, a3);
            b0 = fmaf(fmaxf(qb.x + k0.x, 0.f), w4.x, b0);
            b1 = fmaf(fmaxf(qb.x + k0.y, 0.f), w4.x, b1);
            b2 = fmaf(fmaxf(qb.y + k1.x, 0.f), w4.y, b2);
            b3 = fmaf(fmaxf(qb.y + k1.y, 0.f), w4.y, b3);
            b0 = fmaf(fmaxf(qb.z + k2.x, 0.f), w4.z, b0);
            b1 = fmaf(fmaxf(qb.z + k2.y, 0.f), w4.z, b1);
            b2 = fmaf(fmaxf(qb.w + k3.x, 0.f), w4.w, b2);
            b3 = fmaf(fmaxf(qb.w + k3.y, 0.f), w4.w, b3);
        }
        const int j = j0 + 2 * lane;
        float s0a = (j     <= ia) ? (a0 + a2) : NEG_INF;
        float s1a = (j + 1 <= ia) ? (a1 + a3) : NEG_INF;
        float s0b = (j     <= ib) ? (b0 + b2) : NEG_INF;
        float s1b = (j + 1 <= ib) ? (b1 + b3) : NEG_INF;

        float nma  = fmaxf(ma, warp_max_f32(fmaxf(s0a, s1a)));
        float nmb  = fmaxf(mb, warp_max_f32(fmaxf(s0b, s1b)));
        float ca   = __expf(ma - nma);
        float cb   = __expf(mb - nmb);
        float p0a  = __expf(s0a - nma), p1a = __expf(s1a - nma);
        float p0b  = __expf(s0b - nmb), p1b = __expf(s1b - nmb);
        la = fmaf(la, ca, p0a + p1a);
        lb = fmaf(lb, cb, p0b + p1b);
        axe *= ca; aye *= ca; axo *= ca; ayo *= ca;
        bxe *= cb; bye *= cb; bxo *= cb; byo *= cb;
        ma = nma; mb = nmb;

        *(float2*)&p_s[wid * 2    ][2 * lane] = make_float2(p0a, p1a);
        *(float2*)&p_s[wid * 2 + 1][2 * lane] = make_float2(p0b, p1b);
        __syncwarp();

        #pragma unroll
        for (int jj = 0; jj < JCH; jj += 2) {
            float  pae = p_s[wid * 2][jj];
            float  pao = p_s[wid * 2][jj + 1];
            float  pbe = p_s[wid * 2 + 1][jj];
            float  pbo = p_s[wid * 2 + 1][jj + 1];
            float2 ve = *(const float2*)&vv_s[jj][2 * lane];
            float2 vo = *(const float2*)&vv_s[jj + 1][2 * lane];
            axe = fmaf(pae, ve.x, axe);
            aye = fmaf(pae, ve.y, aye);
            axo = fmaf(pao, vo.x, axo);
            ayo = fmaf(pao, vo.y, ayo);
            bxe = fmaf(pbe, ve.x, bxe);
            bye = fmaf(pbe, ve.y, bye);
            bxo = fmaf(pbo, vo.x, bxo);
            byo = fmaf(pbo, vo.y, byo);
        }
    }

    float lta = la, ltb = lb;
    #pragma unroll
    for (int off = 16; off; off >>= 1) {
        lta += __shfl_xor_sync(0xffffffffu, lta, off);
        ltb += __shfl_xor_sync(0xffffffffu, ltb, off);
    }

    *(float2*)&g_po[s][(b * TT + ia) * DD + 2 * lane] = make_float2(axe + axo, aye + ayo);
    *(float2*)&g_po[s][(b * TT + ib) * DD + 2 * lane] = make_float2(bxe + bxo, bye + byo);
    if (lane == 0) {
        g_pm[s][b * TT + ia] = ma;  g_pl[s][b * TT + ia] = lta;
        g_pm[s][b * TT + ib] = mb;  g_pl[s][b * TT + ib] = ltb;
    }
}

// ---------------------------------------------------------------------------
// Kernel 3: combine the two split-K partials.
// ---------------------------------------------------------------------------
__global__ __launch_bounds__(128) void combine_kernel(float* __restrict__ out)
{
    const int row  = blockIdx.x * 4 + (threadIdx.x >> 5);
    const int lane = threadIdx.x & 31;

    float m0 = g_pm[0][row], l0 = g_pl[0][row];
    float m1 = g_pm[1][row], l1 = g_pl[1][row];
    float M  = fmaxf(m0, m1);
    float c0 = __expf(m0 - M);
    float c1 = __expf(m1 - M);
    float inv = 1.0f / fmaf(l0, c0, l1 * c1);

    float2 o0 = *(const float2*)&g_po[0][row * DD + 2 * lane];
    float2 o1 = *(const float2*)&g_po[1][row * DD + 2 * lane];
    *(float2*)&out[row * DD + 2 * lane] =
        make_float2(fmaf(o0.x, c0, o1.x * c1) * inv,
                    fmaf(o0.y, c0, o1.y * c1) * inv);
}

// ---------------------------------------------------------------------------
extern "C" void kernel_launch(void* const* d_in, const int* in_sizes, int n_in,
                              void* d_out, int out_size)
{
    const float* x  = (const float*)d_in[0];
    const float* Wq = (const float*)d_in[1];
    const float* bq = (const float*)d_in[2];
    const float* Wk = (const float*)d_in[3];
    const float* bk = (const float*)d_in[4];
    const float* Wv = (const float*)d_in[5];
    const float* bv = (const float*)d_in[6];
    const float* W1 = (const float*)d_in[7];
    const float* b1 = (const float*)d_in[8];
    const float* W2 = (const float*)d_in[9];
    // b2 (d_in[10]) is a constant shift on scores: cancels in softmax.

    (void)cudaFuncSetAttribute(proj_kernel,
                               cudaFuncAttributeMaxDynamicSharedMemorySize,
                               PROJ_SMEM_BYTES);
    (void)cudaFuncSetAttribute(attn_kernel,
                               cudaFuncAttributeMaxDynamicSharedMemorySize,
                               SMEM_BYTES);

    proj_kernel<<<BB * TT / PROWS, 192, PROJ_SMEM_BYTES>>>(
        x, Wq, bq, Wk, bk, Wv, bv, W1, b1);
    attn_kernel<<<BB * TT / 4 * 2, 64, SMEM_BYTES>>>(W2);
    combine_kernel<<<BB * TT / 4, 128>>>((float*)d_out);
}